// round 2
// baseline (speedup 1.0000x reference)
#include <cuda_runtime.h>

#define NUSERS  500000
#define NPAPERS 100000
#define EMB     64
#define NEDGE   1250000
#define NUD     (NUSERS * EMB)    // 32,000,000 floats (128 MB)
#define NPD     (NPAPERS * EMB)   //  6,400,000 floats (25.6 MB)

// ---------------- scratch (static device globals; no runtime allocation) ----
// One layer buffer per node type (xu_next only reads xp, xp_next only reads xu,
// so no ping-pong needed). Running sums live in d_out directly.
__device__ __align__(256) float g_xu[NUD];
__device__ __align__(256) float g_xp[NPD];
__device__ __align__(256) float g_sc_er[NUSERS];
__device__ __align__(256) float g_sc_ew[NUSERS];
__device__ __align__(256) float g_sc_rr[NPAPERS];
__device__ __align__(256) float g_sc_rw[NPAPERS];

// ---------------- kernels ---------------------------------------------------

__global__ void k_zero4(float4* __restrict__ p, int n4) {
    int i = blockIdx.x * blockDim.x + threadIdx.x;
    if (i < n4) p[i] = make_float4(0.f, 0.f, 0.f, 0.f);
}

// degree count via float atomics (degrees << 2^24 so fp32 add is exact)
__global__ void k_count(const int* __restrict__ src, float* __restrict__ cnt, int n) {
    int i = blockIdx.x * blockDim.x + threadIdx.x;
    if (i < n) atomicAdd(&cnt[src[i]], 1.0f);
}

// sc[i] = 0.5 / max(deg, 1)   (folds normalization AND the 0.5*(r+w) combine)
__global__ void k_mkscale(float* __restrict__ sc, int n) {
    int i = blockIdx.x * blockDim.x + threadIdx.x;
    if (i < n) sc[i] = 0.5f / fmaxf(sc[i], 1.0f);
}

// out[i] = in[i] * s   (sum init: out = 0.25 * layer-0 embedding)
__global__ void k_copyscale(const float4* __restrict__ in, float4* __restrict__ out,
                            float s, int n4) {
    int i = blockIdx.x * blockDim.x + threadIdx.x;
    if (i < n4) {
        float4 v = in[i];
        v.x *= s; v.y *= s; v.z *= s; v.w *= s;
        out[i] = v;
    }
}

// acc[i] += s * x[i]   (running-mean accumulation with the 1/4 folded in)
__global__ void k_accumscale(float4* __restrict__ acc, const float4* __restrict__ x,
                             float s, int n4) {
    int i = blockIdx.x * blockDim.x + threadIdx.x;
    if (i < n4) {
        float4 a = acc[i], b = x[i];
        a.x += s * b.x; a.y += s * b.y; a.z += s * b.z; a.w += s * b.w;
        acc[i] = a;
    }
}

// Scatter: for each edge e, out[src[e]] += sc[src[e]] * xdst[dst[e]]
// 16 threads per edge, float4 per thread (64 floats = one embedding row).
// Gather = two coalesced 128B lines per edge; scatter = vector RED.ADD.F32.128
// (atomicAdd(float4*) with unused return lowers to the no-return RED path).
__global__ void k_scatter(const int* __restrict__ src, const int* __restrict__ dst,
                          const float* __restrict__ xdst, const float* __restrict__ sc,
                          float* __restrict__ out, int n_edges) {
    int g = blockIdx.x * blockDim.x + threadIdx.x;
    int e = g >> 4;
    int t = g & 15;
    if (e >= n_edges) return;
    int s = __ldg(&src[e]);
    int d = __ldg(&dst[e]);
    float scale = __ldg(&sc[s]);
    float4 v = ((const float4*)(xdst + (size_t)d * EMB))[t];
    v.x *= scale; v.y *= scale; v.z *= scale; v.w *= scale;
    atomicAdd(((float4*)(out + (size_t)s * EMB)) + t, v);
}

// ---------------- host driver ----------------------------------------------

static inline int cdiv(long a, int b) { return (int)((a + b - 1) / b); }

extern "C" void kernel_launch(void* const* d_in, const int* in_sizes, int n_in,
                              void* d_out, int out_size) {
    const float* user_emb  = (const float*)d_in[0];   // [500000, 64]
    const float* paper_emb = (const float*)d_in[1];   // [100000, 64]
    const int*   er = (const int*)d_in[2];            // [2, 1.25M]: row0 user, row1 paper
    const int*   ew = (const int*)d_in[3];
    const int*   rr = (const int*)d_in[4];            // [2, 1.25M]: row0 paper, row1 user
    const int*   rw = (const int*)d_in[5];
    float* out   = (float*)d_out;        // running sum for users lives here
    float* out_p = out + NUD;            // running sum for papers

    float *xu, *xp, *sc_er, *sc_ew, *sc_rr, *sc_rw;
    cudaGetSymbolAddress((void**)&xu,    g_xu);
    cudaGetSymbolAddress((void**)&xp,    g_xp);
    cudaGetSymbolAddress((void**)&sc_er, g_sc_er);
    cudaGetSymbolAddress((void**)&sc_ew, g_sc_ew);
    cudaGetSymbolAddress((void**)&sc_rr, g_sc_rr);
    cudaGetSymbolAddress((void**)&sc_rw, g_sc_rw);

    const int T = 256;
    const int nud4 = NUD / 4, npd4 = NPD / 4;
    const float Q = 0.25f;  // mean over 4 snapshots

    // ---- degree -> per-edge-set scale (layer invariant) ----
    k_zero4<<<cdiv(NUSERS / 4, T), T>>>((float4*)sc_er, NUSERS / 4);
    k_zero4<<<cdiv(NUSERS / 4, T), T>>>((float4*)sc_ew, NUSERS / 4);
    k_zero4<<<cdiv(NPAPERS / 4, T), T>>>((float4*)sc_rr, NPAPERS / 4);
    k_zero4<<<cdiv(NPAPERS / 4, T), T>>>((float4*)sc_rw, NPAPERS / 4);
    k_count<<<cdiv(NEDGE, T), T>>>(er, sc_er, NEDGE);
    k_count<<<cdiv(NEDGE, T), T>>>(ew, sc_ew, NEDGE);
    k_count<<<cdiv(NEDGE, T), T>>>(rr, sc_rr, NEDGE);
    k_count<<<cdiv(NEDGE, T), T>>>(rw, sc_rw, NEDGE);
    k_mkscale<<<cdiv(NUSERS, T), T>>>(sc_er, NUSERS);
    k_mkscale<<<cdiv(NUSERS, T), T>>>(sc_ew, NUSERS);
    k_mkscale<<<cdiv(NPAPERS, T), T>>>(sc_rr, NPAPERS);
    k_mkscale<<<cdiv(NPAPERS, T), T>>>(sc_rw, NPAPERS);

    // ---- init running means with 0.25 * layer-0 embeddings (in d_out) ----
    k_copyscale<<<cdiv(nud4, T), T>>>((const float4*)user_emb,  (float4*)out,   Q, nud4);
    k_copyscale<<<cdiv(npd4, T), T>>>((const float4*)paper_emb, (float4*)out_p, Q, npd4);

    // ---- 3 propagation layers ----
    const float* xp_cur = paper_emb;     // layer 0 reads the input embeddings
    const int sgrid = cdiv((long)NEDGE * 16, T);

    for (int l = 0; l < 3; l++) {
        // users <- papers   (xu only reads xp_cur, so overwriting xu is safe)
        k_zero4<<<cdiv(nud4, T), T>>>((float4*)xu, nud4);
        k_scatter<<<sgrid, T>>>(er, er + NEDGE, xp_cur, sc_er, xu, NEDGE);
        k_scatter<<<sgrid, T>>>(ew, ew + NEDGE, xp_cur, sc_ew, xu, NEDGE);
        k_accumscale<<<cdiv(nud4, T), T>>>((float4*)out, (const float4*)xu, Q, nud4);

        // papers <- (new) users   (xp only reads xu, so overwriting xp is safe)
        k_zero4<<<cdiv(npd4, T), T>>>((float4*)xp, npd4);
        k_scatter<<<sgrid, T>>>(rr, rr + NEDGE, xu, sc_rr, xp, NEDGE);
        k_scatter<<<sgrid, T>>>(rw, rw + NEDGE, xu, sc_rw, xp, NEDGE);
        k_accumscale<<<cdiv(npd4, T), T>>>((float4*)out_p, (const float4*)xp, Q, npd4);

        xp_cur = xp;
    }
    (void)in_sizes; (void)n_in; (void)out_size;
}

// round 3
// speedup vs baseline: 1.6883x; 1.6883x over previous
#include <cuda_runtime.h>

#define NUSERS  500000
#define NPAPERS 100000
#define EMB     64
#define NEDGE   1250000
#define NUD     (NUSERS * EMB)
#define NPD     (NPAPERS * EMB)
#define SCAN_B  1024

// ---------------- static scratch (no runtime allocation) --------------------
__device__ __align__(256) float g_xu[NUD];            // 128 MB
__device__ __align__(256) float g_xp[NPD];            // 25.6 MB
__device__ __align__(256) int g_col_er[NEDGE];
__device__ __align__(256) int g_col_ew[NEDGE];
__device__ __align__(256) int g_col_rr[NEDGE];
__device__ __align__(256) int g_col_rw[NEDGE];
__device__ __align__(256) int g_rp_er[NUSERS + 1];
__device__ __align__(256) int g_rp_ew[NUSERS + 1];
__device__ __align__(256) int g_rp_rr[NPAPERS + 1];
__device__ __align__(256) int g_rp_rw[NPAPERS + 1];
__device__ __align__(256) int g_cnt[NUSERS];          // reused per set
__device__ __align__(256) int g_cur[NUSERS];          // binning cursor, reused
__device__ __align__(256) int g_btot[SCAN_B];         // block totals (<=489 blocks)

// ---------------- CSR build kernels -----------------------------------------

__global__ void k_zero_int(int* __restrict__ p, int n) {
    int i = blockIdx.x * blockDim.x + threadIdx.x;
    if (i < n) p[i] = 0;
}

__global__ void k_hist(const int* __restrict__ src, int* __restrict__ cnt, int n) {
    int i = blockIdx.x * blockDim.x + threadIdx.x;
    if (i < n) atomicAdd(&cnt[src[i]], 1);
}

// block-level exclusive scan; writes local-exclusive into rp, block total into btot
__global__ void k_scan1(const int* __restrict__ cnt, int* __restrict__ rp,
                        int* __restrict__ btot, int n) {
    __shared__ int sm[SCAN_B];
    int i = blockIdx.x * SCAN_B + threadIdx.x;
    int v = (i < n) ? cnt[i] : 0;
    sm[threadIdx.x] = v;
    __syncthreads();
    for (int off = 1; off < SCAN_B; off <<= 1) {
        int t = (threadIdx.x >= off) ? sm[threadIdx.x - off] : 0;
        __syncthreads();
        sm[threadIdx.x] += t;
        __syncthreads();
    }
    if (i < n) rp[i] = sm[threadIdx.x] - v;           // exclusive
    if (threadIdx.x == SCAN_B - 1) btot[blockIdx.x] = sm[threadIdx.x];
}

// single-block exclusive scan of block totals, in place
__global__ void k_scan2(int* __restrict__ btot, int nb) {
    __shared__ int sm[SCAN_B];
    int v = (threadIdx.x < nb) ? btot[threadIdx.x] : 0;
    sm[threadIdx.x] = v;
    __syncthreads();
    for (int off = 1; off < SCAN_B; off <<= 1) {
        int t = (threadIdx.x >= off) ? sm[threadIdx.x - off] : 0;
        __syncthreads();
        sm[threadIdx.x] += t;
        __syncthreads();
    }
    if (threadIdx.x < nb) btot[threadIdx.x] = sm[threadIdx.x] - v;
}

// add block offsets; also seed cursor and write rp[n]=total
__global__ void k_addback(int* __restrict__ rp, const int* __restrict__ boff,
                          int* __restrict__ cur, int n, int total) {
    int i = blockIdx.x * blockDim.x + threadIdx.x;
    if (i < n) {
        int r = rp[i] + boff[i >> 10];
        rp[i] = r;
        cur[i] = r;
    }
    if (i == 0) rp[n] = total;
}

__global__ void k_bin(const int* __restrict__ src, const int* __restrict__ dst,
                      int* __restrict__ cur, int* __restrict__ col, int n) {
    int i = blockIdx.x * blockDim.x + threadIdx.x;
    if (i < n) {
        int pos = atomicAdd(&cur[src[i]], 1);
        col[pos] = dst[i];
    }
}

// ---------------- fused pull-propagation kernel ------------------------------
// Per node: gather+sum neighbors over both edge sets (A=read-like, B=write-like),
// v = 0.5*(sumA/degA + sumB/degB); write layer buffer; update running mean.
// 16 threads per node, one float4 lane-chunk each (64 floats = full row).
__global__ void k_prop(const int* __restrict__ rpA, const int* __restrict__ colA,
                       const int* __restrict__ rpB, const int* __restrict__ colB,
                       const float* __restrict__ xsrc,
                       const float* __restrict__ base,   // layer-0 emb or nullptr
                       float* __restrict__ xout, float* __restrict__ osum,
                       int nnodes) {
    int node = blockIdx.x * (blockDim.x >> 4) + (threadIdx.x >> 4);
    int t = threadIdx.x & 15;
    if (node >= nnodes) return;

    float4 a = make_float4(0.f, 0.f, 0.f, 0.f);
    int s0 = __ldg(&rpA[node]), e0 = __ldg(&rpA[node + 1]);
    for (int j = s0; j < e0; j++) {
        int d = __ldg(&colA[j]);
        float4 m = __ldg(((const float4*)(xsrc + (size_t)d * EMB)) + t);
        a.x += m.x; a.y += m.y; a.z += m.z; a.w += m.w;
    }
    float4 b = make_float4(0.f, 0.f, 0.f, 0.f);
    int s1 = __ldg(&rpB[node]), e1 = __ldg(&rpB[node + 1]);
    for (int j = s1; j < e1; j++) {
        int d = __ldg(&colB[j]);
        float4 m = __ldg(((const float4*)(xsrc + (size_t)d * EMB)) + t);
        b.x += m.x; b.y += m.y; b.z += m.z; b.w += m.w;
    }

    float ia = 0.5f / fmaxf((float)(e0 - s0), 1.f);
    float ib = 0.5f / fmaxf((float)(e1 - s1), 1.f);
    float4 v = make_float4(a.x * ia + b.x * ib, a.y * ia + b.y * ib,
                           a.z * ia + b.z * ib, a.w * ia + b.w * ib);

    size_t off = (size_t)node * EMB;
    ((float4*)(xout + off))[t] = v;

    float4 o;
    if (base) {                                   // layer 1: o = 0.25*(emb + v)
        float4 e = __ldg(((const float4*)(base + off)) + t);
        o = make_float4(0.25f * (e.x + v.x), 0.25f * (e.y + v.y),
                        0.25f * (e.z + v.z), 0.25f * (e.w + v.w));
    } else {                                      // layers 2,3: o += 0.25*v
        o = ((const float4*)(osum + off))[t];
        o.x += 0.25f * v.x; o.y += 0.25f * v.y;
        o.z += 0.25f * v.z; o.w += 0.25f * v.w;
    }
    ((float4*)(osum + off))[t] = o;
}

// ---------------- host driver ------------------------------------------------

static inline int cdiv(long a, int b) { return (int)((a + b - 1) / b); }

static void build_csr(const int* edges, int* rp, int* col, int* cnt, int* cur,
                      int* btot, int nnodes) {
    const int T = 256;
    const int* src = edges;
    const int* dst = edges + NEDGE;
    int nb = cdiv(nnodes, SCAN_B);
    k_zero_int<<<cdiv(nnodes, T), T>>>(cnt, nnodes);
    k_hist<<<cdiv(NEDGE, T), T>>>(src, cnt, NEDGE);
    k_scan1<<<nb, SCAN_B>>>(cnt, rp, btot, nnodes);
    k_scan2<<<1, SCAN_B>>>(btot, nb);
    k_addback<<<cdiv(nnodes, T), T>>>(rp, btot, cur, nnodes, NEDGE);
    k_bin<<<cdiv(NEDGE, T), T>>>(src, dst, cur, col, NEDGE);
}

extern "C" void kernel_launch(void* const* d_in, const int* in_sizes, int n_in,
                              void* d_out, int out_size) {
    const float* user_emb  = (const float*)d_in[0];   // [500000, 64]
    const float* paper_emb = (const float*)d_in[1];   // [100000, 64]
    const int*   er = (const int*)d_in[2];            // row0 user, row1 paper
    const int*   ew = (const int*)d_in[3];
    const int*   rr = (const int*)d_in[4];            // row0 paper, row1 user
    const int*   rw = (const int*)d_in[5];
    float* out_u = (float*)d_out;
    float* out_p = out_u + NUD;

    float *xu, *xp;
    int *col_er, *col_ew, *col_rr, *col_rw;
    int *rp_er, *rp_ew, *rp_rr, *rp_rw, *cnt, *cur, *btot;
    cudaGetSymbolAddress((void**)&xu, g_xu);
    cudaGetSymbolAddress((void**)&xp, g_xp);
    cudaGetSymbolAddress((void**)&col_er, g_col_er);
    cudaGetSymbolAddress((void**)&col_ew, g_col_ew);
    cudaGetSymbolAddress((void**)&col_rr, g_col_rr);
    cudaGetSymbolAddress((void**)&col_rw, g_col_rw);
    cudaGetSymbolAddress((void**)&rp_er, g_rp_er);
    cudaGetSymbolAddress((void**)&rp_ew, g_rp_ew);
    cudaGetSymbolAddress((void**)&rp_rr, g_rp_rr);
    cudaGetSymbolAddress((void**)&rp_rw, g_rp_rw);
    cudaGetSymbolAddress((void**)&cnt,  g_cnt);
    cudaGetSymbolAddress((void**)&cur,  g_cur);
    cudaGetSymbolAddress((void**)&btot, g_btot);

    // ---- build layer-invariant CSRs (4 edge sets) ----
    build_csr(er, rp_er, col_er, cnt, cur, btot, NUSERS);
    build_csr(ew, rp_ew, col_ew, cnt, cur, btot, NUSERS);
    build_csr(rr, rp_rr, col_rr, cnt, cur, btot, NPAPERS);
    build_csr(rw, rp_rw, col_rw, cnt, cur, btot, NPAPERS);

    // ---- 3 propagation layers, fully fused (no zero/accum/final passes) ----
    const int T = 256;                   // 16 nodes per block
    const int gu = cdiv(NUSERS, T / 16);
    const int gp = cdiv(NPAPERS, T / 16);

    const float* xp_cur = paper_emb;
    for (int l = 0; l < 3; l++) {
        const float* base_u = (l == 0) ? user_emb : nullptr;
        const float* base_p = (l == 0) ? paper_emb : nullptr;
        // users <- papers
        k_prop<<<gu, T>>>(rp_er, col_er, rp_ew, col_ew, xp_cur, base_u,
                          xu, out_u, NUSERS);
        // papers <- (new) users
        k_prop<<<gp, T>>>(rp_rr, col_rr, rp_rw, col_rw, xu, base_p,
                          xp, out_p, NPAPERS);
        xp_cur = xp;
    }
    (void)in_sizes; (void)n_in; (void)out_size;
}

// round 5
// speedup vs baseline: 2.1735x; 1.2874x over previous
#include <cuda_runtime.h>
#include <cuda_fp16.h>

#define NUSERS  500000
#define NPAPERS 100000
#define EMB     64
#define NEDGE   1250000
#define NUD     (NUSERS * EMB)
#define NPD     (NPAPERS * EMB)
#define SCAN_B  1024

// ---------------- static scratch (~102 MB total; keep < ~200 MB) ------------
__device__ __align__(256) __half g_xu[NUD];            // 64 MB
__device__ __align__(256) __half g_xp[NPD];            // 12.8 MB
__device__ __align__(256) int g_col_er[NEDGE];         // 5 MB each
__device__ __align__(256) int g_col_ew[NEDGE];
__device__ __align__(256) int g_col_rr[NEDGE];
__device__ __align__(256) int g_col_rw[NEDGE];
__device__ __align__(256) int g_rp_er[NUSERS + 1];
__device__ __align__(256) int g_rp_ew[NUSERS + 1];
__device__ __align__(256) int g_rp_rr[NPAPERS + 1];
__device__ __align__(256) int g_rp_rw[NPAPERS + 1];
__device__ __align__(256) int g_cur_er[NUSERS];
__device__ __align__(256) int g_cur_ew[NUSERS];
__device__ __align__(256) int g_cur_rr[NPAPERS];
__device__ __align__(256) int g_cur_rw[NPAPERS];
__device__ __align__(256) int g_btot[4][SCAN_B];

// ---------------- CSR build --------------------------------------------------

__global__ void k_zero_int(int* __restrict__ p, int n) {
    int i = blockIdx.x * blockDim.x + threadIdx.x;
    if (i < n) p[i] = 0;
}

// fused histogram over all 4 edge sets (rp arrays double as counters)
__global__ void k_hist4(const int* __restrict__ e0, const int* __restrict__ e1,
                        const int* __restrict__ e2, const int* __restrict__ e3,
                        int* __restrict__ c0, int* __restrict__ c1,
                        int* __restrict__ c2, int* __restrict__ c3) {
    int i = blockIdx.x * blockDim.x + threadIdx.x;
    if (i >= 4 * NEDGE) return;
    int set = i / NEDGE;
    int j = i - set * NEDGE;
    const int* e = (set == 0) ? e0 : (set == 1) ? e1 : (set == 2) ? e2 : e3;
    int*       c = (set == 0) ? c0 : (set == 1) ? c1 : (set == 2) ? c2 : c3;
    atomicAdd(&c[e[j]], 1);
}

__global__ void k_scan1(int* __restrict__ rp, int* __restrict__ btot, int n) {
    __shared__ int sm[SCAN_B];
    int i = blockIdx.x * SCAN_B + threadIdx.x;
    int v = (i < n) ? rp[i] : 0;
    sm[threadIdx.x] = v;
    __syncthreads();
    for (int off = 1; off < SCAN_B; off <<= 1) {
        int t = (threadIdx.x >= off) ? sm[threadIdx.x - off] : 0;
        __syncthreads();
        sm[threadIdx.x] += t;
        __syncthreads();
    }
    if (i < n) rp[i] = sm[threadIdx.x] - v;            // exclusive
    if (threadIdx.x == SCAN_B - 1) btot[blockIdx.x] = sm[threadIdx.x];
}

__global__ void k_scan2(int* __restrict__ btot, int nb) {
    __shared__ int sm[SCAN_B];
    int v = (threadIdx.x < nb) ? btot[threadIdx.x] : 0;
    sm[threadIdx.x] = v;
    __syncthreads();
    for (int off = 1; off < SCAN_B; off <<= 1) {
        int t = (threadIdx.x >= off) ? sm[threadIdx.x - off] : 0;
        __syncthreads();
        sm[threadIdx.x] += t;
        __syncthreads();
    }
    if (threadIdx.x < nb) btot[threadIdx.x] = sm[threadIdx.x] - v;
}

__global__ void k_addback(int* __restrict__ rp, const int* __restrict__ boff,
                          int* __restrict__ cur, int n, int total) {
    int i = blockIdx.x * blockDim.x + threadIdx.x;
    if (i < n) {
        int r = rp[i] + boff[i >> 10];
        rp[i] = r;
        cur[i] = r;
    }
    if (i == 0) rp[n] = total;
}

// fused binning over all 4 edge sets
__global__ void k_bin4(const int* __restrict__ e0, const int* __restrict__ e1,
                       const int* __restrict__ e2, const int* __restrict__ e3,
                       int* __restrict__ u0, int* __restrict__ u1,
                       int* __restrict__ u2, int* __restrict__ u3,
                       int* __restrict__ o0, int* __restrict__ o1,
                       int* __restrict__ o2, int* __restrict__ o3) {
    int i = blockIdx.x * blockDim.x + threadIdx.x;
    if (i >= 4 * NEDGE) return;
    int set = i / NEDGE;
    int j = i - set * NEDGE;
    const int* e = (set == 0) ? e0 : (set == 1) ? e1 : (set == 2) ? e2 : e3;
    int*       u = (set == 0) ? u0 : (set == 1) ? u1 : (set == 2) ? u2 : u3;
    int*       o = (set == 0) ? o0 : (set == 1) ? o1 : (set == 2) ? o2 : o3;
    int pos = atomicAdd(&u[e[j]], 1);
    o[pos] = e[j + NEDGE];                              // dst index
}

// ---------------- pull propagation (fused running mean) ----------------------
// 16 threads per node, thread t owns embedding elems [4t, 4t+4).
// Gathers both edge sets from xsrc, v = 0.5*(sumA/degA + sumB/degB),
// writes fp16 layer row, and updates the fp32 running mean in osum (d_out):
//   FIRST:  osum = 0.25*(base + v)        (layer 1, base = input embedding)
//   else:   osum += 0.25*v                (layers 2, 3)
template <bool SRC_HALF, bool FIRST>
__global__ void k_prop(const int* __restrict__ rpA, const int* __restrict__ colA,
                       const int* __restrict__ rpB, const int* __restrict__ colB,
                       const void* __restrict__ xsrc_,
                       const float* __restrict__ base,
                       __half* __restrict__ xout,
                       float* __restrict__ osum, int nnodes) {
    int node = blockIdx.x * (blockDim.x >> 4) + (threadIdx.x >> 4);
    int t = threadIdx.x & 15;
    if (node >= nnodes) return;

    float a0 = 0.f, a1 = 0.f, a2 = 0.f, a3 = 0.f;
    float b0 = 0.f, b1 = 0.f, b2 = 0.f, b3 = 0.f;

    int s0 = __ldg(&rpA[node]), e0 = __ldg(&rpA[node + 1]);
    for (int j = s0; j < e0; j++) {
        int d = __ldg(&colA[j]);
        if (SRC_HALF) {
            const __half* p = (const __half*)xsrc_ + (size_t)d * EMB + t * 4;
            uint2 u = __ldg((const uint2*)p);
            float2 f0 = __half22float2(*(const half2*)&u.x);
            float2 f1 = __half22float2(*(const half2*)&u.y);
            a0 += f0.x; a1 += f0.y; a2 += f1.x; a3 += f1.y;
        } else {
            float4 m = __ldg(((const float4*)((const float*)xsrc_ + (size_t)d * EMB)) + t);
            a0 += m.x; a1 += m.y; a2 += m.z; a3 += m.w;
        }
    }
    int s1 = __ldg(&rpB[node]), e1 = __ldg(&rpB[node + 1]);
    for (int j = s1; j < e1; j++) {
        int d = __ldg(&colB[j]);
        if (SRC_HALF) {
            const __half* p = (const __half*)xsrc_ + (size_t)d * EMB + t * 4;
            uint2 u = __ldg((const uint2*)p);
            float2 f0 = __half22float2(*(const half2*)&u.x);
            float2 f1 = __half22float2(*(const half2*)&u.y);
            b0 += f0.x; b1 += f0.y; b2 += f1.x; b3 += f1.y;
        } else {
            float4 m = __ldg(((const float4*)((const float*)xsrc_ + (size_t)d * EMB)) + t);
            b0 += m.x; b1 += m.y; b2 += m.z; b3 += m.w;
        }
    }

    float ia = 0.5f / fmaxf((float)(e0 - s0), 1.f);
    float ib = 0.5f / fmaxf((float)(e1 - s1), 1.f);
    float v0 = a0 * ia + b0 * ib;
    float v1 = a1 * ia + b1 * ib;
    float v2 = a2 * ia + b2 * ib;
    float v3 = a3 * ia + b3 * ib;

    size_t off = (size_t)node * EMB + t * 4;

    // fp16 layer write
    half2 h0 = __floats2half2_rn(v0, v1);
    half2 h1 = __floats2half2_rn(v2, v3);
    uint2 u;
    u.x = *(const unsigned int*)&h0;
    u.y = *(const unsigned int*)&h1;
    *((uint2*)(xout + off)) = u;

    // running-mean update in d_out (fp32)
    float4 o;
    if (FIRST) {
        float4 e = __ldg((const float4*)(base + off));
        o.x = 0.25f * (e.x + v0);
        o.y = 0.25f * (e.y + v1);
        o.z = 0.25f * (e.z + v2);
        o.w = 0.25f * (e.w + v3);
    } else {
        o = *((const float4*)(osum + off));
        o.x += 0.25f * v0;
        o.y += 0.25f * v1;
        o.z += 0.25f * v2;
        o.w += 0.25f * v3;
    }
    *((float4*)(osum + off)) = o;
}

// ---------------- host driver ------------------------------------------------

static inline int cdiv(long a, int b) { return (int)((a + b - 1) / b); }

extern "C" void kernel_launch(void* const* d_in, const int* in_sizes, int n_in,
                              void* d_out, int out_size) {
    const float* user_emb  = (const float*)d_in[0];
    const float* paper_emb = (const float*)d_in[1];
    const int*   er = (const int*)d_in[2];   // row0 user, row1 paper
    const int*   ew = (const int*)d_in[3];
    const int*   rr = (const int*)d_in[4];   // row0 paper, row1 user
    const int*   rw = (const int*)d_in[5];
    float* out_u = (float*)d_out;
    float* out_p = out_u + NUD;

    __half *xu, *xp;
    int *col_er, *col_ew, *col_rr, *col_rw;
    int *rp_er, *rp_ew, *rp_rr, *rp_rw;
    int *cur_er, *cur_ew, *cur_rr, *cur_rw;
    int *btot;
    cudaGetSymbolAddress((void**)&xu, g_xu);
    cudaGetSymbolAddress((void**)&xp, g_xp);
    cudaGetSymbolAddress((void**)&col_er, g_col_er);
    cudaGetSymbolAddress((void**)&col_ew, g_col_ew);
    cudaGetSymbolAddress((void**)&col_rr, g_col_rr);
    cudaGetSymbolAddress((void**)&col_rw, g_col_rw);
    cudaGetSymbolAddress((void**)&rp_er, g_rp_er);
    cudaGetSymbolAddress((void**)&rp_ew, g_rp_ew);
    cudaGetSymbolAddress((void**)&rp_rr, g_rp_rr);
    cudaGetSymbolAddress((void**)&rp_rw, g_rp_rw);
    cudaGetSymbolAddress((void**)&cur_er, g_cur_er);
    cudaGetSymbolAddress((void**)&cur_ew, g_cur_ew);
    cudaGetSymbolAddress((void**)&cur_rr, g_cur_rr);
    cudaGetSymbolAddress((void**)&cur_rw, g_cur_rw);
    cudaGetSymbolAddress((void**)&btot, g_btot);

    const int T = 256;

    // ---- CSR build (layer-invariant) ----
    k_zero_int<<<cdiv(NUSERS + 1, T), T>>>(rp_er, NUSERS + 1);
    k_zero_int<<<cdiv(NUSERS + 1, T), T>>>(rp_ew, NUSERS + 1);
    k_zero_int<<<cdiv(NPAPERS + 1, T), T>>>(rp_rr, NPAPERS + 1);
    k_zero_int<<<cdiv(NPAPERS + 1, T), T>>>(rp_rw, NPAPERS + 1);

    k_hist4<<<cdiv(4L * NEDGE, T), T>>>(er, ew, rr, rw, rp_er, rp_ew, rp_rr, rp_rw);

    int nb_u = cdiv(NUSERS, SCAN_B), nb_p = cdiv(NPAPERS, SCAN_B);
    k_scan1<<<nb_u, SCAN_B>>>(rp_er, btot + 0 * SCAN_B, NUSERS);
    k_scan1<<<nb_u, SCAN_B>>>(rp_ew, btot + 1 * SCAN_B, NUSERS);
    k_scan1<<<nb_p, SCAN_B>>>(rp_rr, btot + 2 * SCAN_B, NPAPERS);
    k_scan1<<<nb_p, SCAN_B>>>(rp_rw, btot + 3 * SCAN_B, NPAPERS);
    k_scan2<<<1, SCAN_B>>>(btot + 0 * SCAN_B, nb_u);
    k_scan2<<<1, SCAN_B>>>(btot + 1 * SCAN_B, nb_u);
    k_scan2<<<1, SCAN_B>>>(btot + 2 * SCAN_B, nb_p);
    k_scan2<<<1, SCAN_B>>>(btot + 3 * SCAN_B, nb_p);
    k_addback<<<cdiv(NUSERS, T), T>>>(rp_er, btot + 0 * SCAN_B, cur_er, NUSERS, NEDGE);
    k_addback<<<cdiv(NUSERS, T), T>>>(rp_ew, btot + 1 * SCAN_B, cur_ew, NUSERS, NEDGE);
    k_addback<<<cdiv(NPAPERS, T), T>>>(rp_rr, btot + 2 * SCAN_B, cur_rr, NPAPERS, NEDGE);
    k_addback<<<cdiv(NPAPERS, T), T>>>(rp_rw, btot + 3 * SCAN_B, cur_rw, NPAPERS, NEDGE);

    k_bin4<<<cdiv(4L * NEDGE, T), T>>>(er, ew, rr, rw,
                                       cur_er, cur_ew, cur_rr, cur_rw,
                                       col_er, col_ew, col_rr, col_rw);

    // ---- 3 propagation layers (fp16 single buffers, mean fused into d_out) --
    const int gu = cdiv(NUSERS, T / 16);
    const int gp = cdiv(NPAPERS, T / 16);

    // layer 1
    k_prop<false, true><<<gu, T>>>(rp_er, col_er, rp_ew, col_ew, paper_emb,
                                   user_emb, xu, out_u, NUSERS);
    k_prop<true, true><<<gp, T>>>(rp_rr, col_rr, rp_rw, col_rw, xu,
                                  paper_emb, xp, out_p, NPAPERS);
    // layers 2, 3
    for (int l = 1; l < 3; l++) {
        k_prop<true, false><<<gu, T>>>(rp_er, col_er, rp_ew, col_ew, xp,
                                       nullptr, xu, out_u, NUSERS);
        k_prop<true, false><<<gp, T>>>(rp_rr, col_rr, rp_rw, col_rw, xu,
                                       nullptr, xp, out_p, NPAPERS);
    }

    (void)in_sizes; (void)n_in; (void)out_size;
}